// round 6
// baseline (speedup 1.0000x reference)
#include <cuda_runtime.h>
#include <cuda_bf16.h>
#include <math.h>
#include <stdint.h>

#define B_  2
#define S_  2048
#define H_  8
#define D_  64
#define DM_ 512
#define W_  128

typedef unsigned long long ull;

// ---------------- scratch (device globals; no allocation) ------------------
__device__ float g_q[B_*H_*S_*D_];
__device__ float g_k[B_*H_*S_*D_];
__device__ float g_v[B_*H_*S_*D_];
// split-bf16 operands (A side: X first, then attention output written by attn_k)
__device__ __nv_bfloat16 g_ah[B_*S_*DM_];
__device__ __nv_bfloat16 g_al[B_*S_*DM_];
__device__ __nv_bfloat16 g_wh[4*DM_*DM_];     // W^T hi: rows 0..1535 Wq,Wk,Wv; 1536.. Wo
__device__ __nv_bfloat16 g_wl[4*DM_*DM_];     // W^T lo

// ---------------- fp32x2 helpers -------------------------------------------
__device__ __forceinline__ ull pack2(float lo, float hi) {
    ull r; asm("mov.b64 %0, {%1, %2};" : "=l"(r) : "f"(lo), "f"(hi)); return r;
}
__device__ __forceinline__ void fma2(ull& d, ull a, ull b) {
    asm("fma.rn.f32x2 %0, %1, %2, %0;" : "+l"(d) : "l"(a), "l"(b));
}
__device__ __forceinline__ float2 unpk(ull v) {
    float2 f; asm("mov.b64 {%0, %1}, %2;" : "=f"(f.x), "=f"(f.y) : "l"(v)); return f;
}

__device__ __forceinline__ uint32_t smem_u32(const void* p) {
    uint32_t a;
    asm("{ .reg .u64 t; cvta.to.shared.u64 t, %1; cvt.u32.u64 %0, t; }" : "=r"(a) : "l"(p));
    return a;
}

// ---------------- mma.sync building blocks (plain sm_103 PTX) --------------
#define LDSM4(r, addr) \
    asm volatile("ldmatrix.sync.aligned.m8n8.x4.shared.b16 {%0,%1,%2,%3}, [%4];" \
        : "=r"((r)[0]), "=r"((r)[1]), "=r"((r)[2]), "=r"((r)[3]) : "r"(addr))

#define MMA16816(c, a, b0, b1) \
    asm volatile("mma.sync.aligned.m16n8k16.row.col.f32.bf16.bf16.f32 " \
        "{%0,%1,%2,%3}, {%4,%5,%6,%7}, {%8,%9}, {%0,%1,%2,%3};" \
        : "+f"((c)[0]), "+f"((c)[1]), "+f"((c)[2]), "+f"((c)[3]) \
        : "r"((a)[0]), "r"((a)[1]), "r"((a)[2]), "r"((a)[3]), "r"(b0), "r"(b1))

__device__ __forceinline__ void cpa16(uint32_t s, const __nv_bfloat16* g) {
    asm volatile("cp.async.ca.shared.global [%0], [%1], 16;" :: "r"(s), "l"(g));
}

// ---------------------------------------------------------------------------
// Conversion kernels
// ---------------------------------------------------------------------------
__global__ void __launch_bounds__(256) conv_split_k(const float* __restrict__ X)
{
    int i = (blockIdx.x * 256 + threadIdx.x) * 4;
    float4 v = *(const float4*)(X + i);
    __nv_bfloat16 h0 = __float2bfloat16(v.x);
    __nv_bfloat16 h1 = __float2bfloat16(v.y);
    __nv_bfloat16 h2 = __float2bfloat16(v.z);
    __nv_bfloat16 h3 = __float2bfloat16(v.w);
    __nv_bfloat16 l0 = __float2bfloat16(v.x - __bfloat162float(h0));
    __nv_bfloat16 l1 = __float2bfloat16(v.y - __bfloat162float(h1));
    __nv_bfloat16 l2 = __float2bfloat16(v.z - __bfloat162float(h2));
    __nv_bfloat16 l3 = __float2bfloat16(v.w - __bfloat162float(h3));
    *(__nv_bfloat162*)(g_ah + i)     = __nv_bfloat162(h0, h1);
    *(__nv_bfloat162*)(g_ah + i + 2) = __nv_bfloat162(h2, h3);
    *(__nv_bfloat162*)(g_al + i)     = __nv_bfloat162(l0, l1);
    *(__nv_bfloat162*)(g_al + i + 2) = __nv_bfloat162(l2, l3);
}

__global__ void __launch_bounds__(256) conv_w_k(const float* __restrict__ Wq,
                                                const float* __restrict__ Wk,
                                                const float* __restrict__ Wv,
                                                const float* __restrict__ Wo)
{
    const float* Wsrc = (blockIdx.z == 0) ? Wq : (blockIdx.z == 1 ? Wk :
                        (blockIdx.z == 2 ? Wv : Wo));
    __shared__ float t[32][33];
    int bn = blockIdx.x * 32;
    int bk = blockIdx.y * 32;
    int lx = threadIdx.x & 31, ly = threadIdx.x >> 5;
#pragma unroll
    for (int i = 0; i < 32; i += 8)
        t[ly + i][lx] = Wsrc[(bk + ly + i) * DM_ + bn + lx];
    __syncthreads();
    int rowbase = blockIdx.z * DM_;
#pragma unroll
    for (int i = 0; i < 32; i += 8) {
        int r = ly + i;
        float x = t[lx][r];
        __nv_bfloat16 h = __float2bfloat16(x);
        __nv_bfloat16 l = __float2bfloat16(x - __bfloat162float(h));
        long idx = (long)(rowbase + bn + r) * DM_ + bk + lx;
        g_wh[idx] = h;
        g_wl[idx] = l;
    }
}

// ---------------------------------------------------------------------------
// mma.sync split-bf16 GEMM (unchanged — part of 158.4us best).
// ---------------------------------------------------------------------------
#define GSM_BYTES (2 * 40960)

__device__ __forceinline__ void stage(uint32_t sb, int st, int m0, int nbase, int k0)
{
    const int tid = threadIdx.x;
#pragma unroll
    for (int i = 0; i < 2; i++) {
        int u = tid + (i << 8);
        int r = u >> 2, seg = u & 3;
        uint32_t so = sb + st * 40960 + r * 80 + seg * 16;
        long ga = (long)(m0 + r) * DM_ + k0 + seg * 8;
        long gb = (long)(nbase + r) * DM_ + k0 + seg * 8;
        cpa16(so,         g_ah + ga);
        cpa16(so + 10240, g_al + ga);
        cpa16(so + 20480, g_wh + gb);
        cpa16(so + 30720, g_wl + gb);
    }
    asm volatile("cp.async.commit_group;" ::: "memory");
}

__device__ __forceinline__ void compute_chunk(uint32_t sb, int st, float acc[2][8][4])
{
    const int lane = threadIdx.x & 31, w = threadIdx.x >> 5;
    const int wM = (w & 3) * 32, wN = (w >> 2) * 64;
    uint32_t base = sb + st * 40960;
    const int arow = wM + (lane & 15);
    const int achk = (lane >> 4) * 16;
    const int brow = wN + ((lane >> 4) ? 8 : 0) + (lane & 7);
    const int bchk = ((lane >> 3) & 1) * 16;

#pragma unroll
    for (int kk = 0; kk < 2; kk++) {
        const uint32_t kb = kk * 32;
        uint32_t a_hi[2][4], a_lo[2][4];
#pragma unroll
        for (int mt = 0; mt < 2; mt++) {
            uint32_t ad = base + (arow + mt * 16) * 80 + kb + achk;
            LDSM4(a_hi[mt], ad);
            LDSM4(a_lo[mt], ad + 10240);
        }
#pragma unroll
        for (int nb = 0; nb < 4; nb++) {
            uint32_t bd = base + 20480 + (brow + nb * 16) * 80 + kb + bchk;
            uint32_t bh[4], bl[4];
            LDSM4(bh, bd);
            LDSM4(bl, bd + 10240);
#pragma unroll
            for (int mt = 0; mt < 2; mt++) {
                MMA16816(acc[mt][nb * 2 + 0], a_hi[mt], bh[0], bh[1]);
                MMA16816(acc[mt][nb * 2 + 0], a_hi[mt], bl[0], bl[1]);
                MMA16816(acc[mt][nb * 2 + 0], a_lo[mt], bh[0], bh[1]);
                MMA16816(acc[mt][nb * 2 + 1], a_hi[mt], bh[2], bh[3]);
                MMA16816(acc[mt][nb * 2 + 1], a_hi[mt], bl[2], bl[3]);
                MMA16816(acc[mt][nb * 2 + 1], a_lo[mt], bh[2], bh[3]);
            }
        }
    }
}

__device__ __forceinline__ void gemm_mainloop(uint32_t sb, int m0, int nbase,
                                              float acc[2][8][4])
{
#pragma unroll
    for (int mt = 0; mt < 2; mt++)
#pragma unroll
        for (int nf = 0; nf < 8; nf++)
#pragma unroll
            for (int e = 0; e < 4; e++) acc[mt][nf][e] = 0.f;

    stage(sb, 0, m0, nbase, 0);
    for (int c = 0; c < 16; c++) {
        if (c < 15) {
            stage(sb, (c + 1) & 1, m0, nbase, (c + 1) * 32);
            asm volatile("cp.async.wait_group 1;" ::: "memory");
        } else {
            asm volatile("cp.async.wait_group 0;" ::: "memory");
        }
        __syncthreads();
        compute_chunk(sb, c & 1, acc);
        __syncthreads();
    }
}

// QKV projection: head-major scatter.
__global__ void __launch_bounds__(256, 2) mma_gemm_qkv()
{
    extern __shared__ char sm[];
    uint32_t sb = smem_u32(sm);
    const int m0 = blockIdx.y << 7;
    const int nbase = blockIdx.x << 7;
    float acc[2][8][4];
    gemm_mainloop(sb, m0, nbase, acc);

    const int lane = threadIdx.x & 31, w = threadIdx.x >> 5;
    const int wM = (w & 3) * 32, wN = (w >> 2) * 64;
#pragma unroll
    for (int mt = 0; mt < 2; mt++) {
        int r0 = m0 + wM + mt * 16 + (lane >> 2);
        int b = r0 >> 11, s = r0 & (S_ - 1);
#pragma unroll
        for (int nb = 0; nb < 4; nb++) {
#pragma unroll
            for (int nf = 0; nf < 2; nf++) {
                float* c = acc[mt][nb * 2 + nf];
                int n = nbase + wN + nb * 16 + nf * 8 + (lane & 3) * 2;
                int mat = n >> 9, cc = n & 511;
                int h = cc >> 6, d = cc & 63;
                float* outp = (mat == 0) ? g_q : (mat == 1 ? g_k : g_v);
                long o0 = (((long)b * H_ + h) * S_ + s) * D_ + d;
                *(float2*)(outp + o0)          = make_float2(c[0], c[1]);
                *(float2*)(outp + o0 + 8 * D_) = make_float2(c[2], c[3]);
            }
        }
    }
}

// Output projection: row-major store to C.
__global__ void __launch_bounds__(256, 2) mma_gemm_out(float* __restrict__ C)
{
    extern __shared__ char sm[];
    uint32_t sb = smem_u32(sm);
    const int m0 = blockIdx.y << 7;
    const int nbase = blockIdx.x << 7;
    float acc[2][8][4];
    gemm_mainloop(sb, m0, 3 * DM_ + nbase, acc);

    const int lane = threadIdx.x & 31, w = threadIdx.x >> 5;
    const int wM = (w & 3) * 32, wN = (w >> 2) * 64;
#pragma unroll
    for (int mt = 0; mt < 2; mt++) {
        int r0 = m0 + wM + mt * 16 + (lane >> 2);
#pragma unroll
        for (int nb = 0; nb < 4; nb++) {
#pragma unroll
            for (int nf = 0; nf < 2; nf++) {
                float* c = acc[mt][nb * 2 + nf];
                int n = nbase + wN + nb * 16 + nf * 8 + (lane & 3) * 2;
                *(float2*)(C + (long)r0 * DM_ + n)       = make_float2(c[0], c[1]);
                *(float2*)(C + (long)(r0 + 8) * DM_ + n) = make_float2(c[2], c[3]);
            }
        }
    }
}

// ---------------------------------------------------------------------------
// Sliding-window attention: 512 threads, halved per-thread tiles (occupancy).
// __expf softmax (MUFU NOT the bottleneck; poly-exp regressed).
// Epilogue writes split-bf16 into g_ah/g_al.
// SMEM: Qs[64][66] | Ks[192][64] | Vs[192][64];  Ss[64][193] aliases Qs+Ks.
// ---------------------------------------------------------------------------
#define ATT_SMEM_FLOATS (64*66 + 192*64 + 192*64)
#define ATT_SMEM_BYTES  (ATT_SMEM_FLOATS * 4)

__global__ void __launch_bounds__(512, 1) attn_k()
{
    extern __shared__ float smf[];
    float* Qs = smf;                 // [64][66]
    float* Ks = smf + 64 * 66;       // [192][64]
    float* Vs = Ks + 192 * 64;       // [192][64]
    float* Ss = smf;                 // [64][193] alias over Qs+Ks

    const int tid = threadIdx.x;
    const int s0 = blockIdx.x << 6;
    const int h  = blockIdx.y;
    const int b  = blockIdx.z;
    const int base = ((b * H_ + h) * S_) * D_;

    // ---- load Q ([q][d], stride 66) ----
#pragma unroll
    for (int it = 0; it < 2; it++) {
        int idx = tid + it * 512;
        int qq = idx >> 4;
        int dc = (idx & 15) << 2;
        float4 qv = *(const float4*)(g_q + base + (s0 + qq) * D_ + dc);
        Qs[qq * 66 + dc + 0] = qv.x;
        Qs[qq * 66 + dc + 1] = qv.y;
        Qs[qq * 66 + dc + 2] = qv.z;
        Qs[qq * 66 + dc + 3] = qv.w;
    }
    // ---- load K / V band (zero-fill below 0) ----
#pragma unroll
    for (int it = 0; it < 6; it++) {
        int idx = tid + it * 512;
        int jr = idx >> 4;
        int dc = (idx & 15) << 2;
        int kg = s0 - (W_ - 1) + jr;
        float4 kv = make_float4(0.f, 0.f, 0.f, 0.f);
        float4 vv = make_float4(0.f, 0.f, 0.f, 0.f);
        if (kg >= 0) {
            kv = *(const float4*)(g_k + base + kg * D_ + dc);
            vv = *(const float4*)(g_v + base + kg * D_ + dc);
        }
        *(float4*)(Ks + jr * 64 + dc) = kv;
        *(float4*)(Vs + jr * 64 + dc) = vv;
    }
    __syncthreads();

    // ---- phase 1: S = Q K^T (f32x2), 4 rows x 6 cols per thread ----
    const int qg = tid & 15;         // q = qg + 16*r
    const int jg = tid >> 4;         // 0..31
    const int jb = jg * 6;
    ull acc2[4][6];
#pragma unroll
    for (int r = 0; r < 4; r++)
#pragma unroll
        for (int u = 0; u < 6; u++) acc2[r][u] = 0ull;

#pragma unroll 8
    for (int d = 0; d < 64; d += 2) {
        ull qv[4];
#pragma unroll
        for (int r = 0; r < 4; r++)
            qv[r] = *(ull*)(&Qs[(qg + 16 * r) * 66 + d]);
#pragma unroll
        for (int u = 0; u < 6; u++) {
            ull kv = *(ull*)(&Ks[(jb + u) * 64 + d]);
            fma2(acc2[0][u], qv[0], kv);
            fma2(acc2[1][u], qv[1], kv);
            fma2(acc2[2][u], qv[2], kv);
            fma2(acc2[3][u], qv[3], kv);
        }
    }
    __syncthreads();   // Qs/Ks dead; Ss may overwrite

    // ---- mask + scale, write Ss ----
#pragma unroll
    for (int r = 0; r < 4; r++) {
        int i  = qg + 16 * r;
        int lo = (i > (W_ - 1) - s0) ? i : ((W_ - 1) - s0);
        int hi = i + (W_ - 1);
#pragma unroll
        for (int u = 0; u < 6; u++) {
            int j = jb + u;
            float2 f = unpk(acc2[r][u]);
            float sv = (f.x + f.y) * 0.125f;
            Ss[i * 193 + j] = (j >= lo && j <= hi) ? sv : -3.0e38f;
        }
    }
    __syncthreads();

    // ---- phase 2: row softmax (16 warps x 4 rows), __expf ----
    {
        const int w = tid >> 5, lane = tid & 31;
#pragma unroll
        for (int rr = 0; rr < 4; rr++) {
            float* row = Ss + ((w << 2) + rr) * 193;
            float m = -3.0e38f;
#pragma unroll
            for (int c = lane; c < 192; c += 32) m = fmaxf(m, row[c]);
#pragma unroll
            for (int msk = 16; msk >= 1; msk >>= 1)
                m = fmaxf(m, __shfl_xor_sync(0xffffffffu, m, msk));
            float ssum = 0.f;
#pragma unroll
            for (int c = lane; c < 192; c += 32) {
                float e = __expf(row[c] - m);
                row[c] = e;
                ssum += e;
            }
#pragma unroll
            for (int msk = 16; msk >= 1; msk >>= 1)
                ssum += __shfl_xor_sync(0xffffffffu, ssum, msk);
            float inv = 1.0f / ssum;
#pragma unroll
            for (int c = lane; c < 192; c += 32) row[c] *= inv;
        }
    }
    __syncthreads();

    // ---- phase 3: O = P V (f32x2), 4 rows x 1 d-pair per thread ----
    {
        const int qg3 = tid & 15;    // q = qg3 + 16*r
        const int dg  = tid >> 4;    // d pair = dg*2 (0..31)
        ull o2[4];
#pragma unroll
        for (int r = 0; r < 4; r++) o2[r] = 0ull;

#pragma unroll 8
        for (int j = 0; j < 192; j++) {
            ull vv = *(ull*)(Vs + j * 64 + dg * 2);
#pragma unroll
            for (int r = 0; r < 4; r++) {
                float p = Ss[(qg3 + 16 * r) * 193 + j];
                fma2(o2[r], pack2(p, p), vv);
            }
        }
#pragma unroll
        for (int r = 0; r < 4; r++) {
            int q = qg3 + 16 * r;
            float2 p0 = unpk(o2[r]);
            long idx = ((long)(b * S_ + s0 + q)) * DM_ + h * D_ + dg * 2;
            __nv_bfloat16 h0 = __float2bfloat16(p0.x);
            __nv_bfloat16 h1 = __float2bfloat16(p0.y);
            __nv_bfloat16 l0 = __float2bfloat16(p0.x - __bfloat162float(h0));
            __nv_bfloat16 l1 = __float2bfloat16(p0.y - __bfloat162float(h1));
            *(__nv_bfloat162*)(g_ah + idx) = __nv_bfloat162(h0, h1);
            *(__nv_bfloat162*)(g_al + idx) = __nv_bfloat162(l0, l1);
        }
    }
}

// ---------------------------------------------------------------------------
extern "C" void kernel_launch(void* const* d_in, const int* in_sizes, int n_in,
                              void* d_out, int out_size)
{
    const float* x  = (const float*)d_in[0];
    const float* Wq = (const float*)d_in[1];
    const float* Wk = (const float*)d_in[2];
    const float* Wv = (const float*)d_in[3];
    const float* Wo = (const float*)d_in[4];
    float* out = (float*)d_out;

    cudaFuncSetAttribute(mma_gemm_qkv, cudaFuncAttributeMaxDynamicSharedMemorySize, GSM_BYTES);
    cudaFuncSetAttribute(mma_gemm_out, cudaFuncAttributeMaxDynamicSharedMemorySize, GSM_BYTES);
    cudaFuncSetAttribute(attn_k, cudaFuncAttributeMaxDynamicSharedMemorySize, ATT_SMEM_BYTES);

    conv_split_k<<<(B_*S_*DM_) / 1024, 256>>>(x);
    conv_w_k<<<dim3(16, 16, 4), 256>>>(Wq, Wk, Wv, Wo);
    mma_gemm_qkv<<<dim3(12, 32), 256, GSM_BYTES>>>();
    attn_k<<<dim3(S_ / 64, H_, B_), 512, ATT_SMEM_BYTES>>>();
    mma_gemm_out<<<dim3(4, 32), 256, GSM_BYTES>>>(out);
}

// round 7
// speedup vs baseline: 1.0849x; 1.0849x over previous
#include <cuda_runtime.h>
#include <cuda_bf16.h>
#include <math.h>
#include <stdint.h>

#define B_  2
#define S_  2048
#define H_  8
#define D_  64
#define DM_ 512
#define W_  128

typedef unsigned long long ull;

// ---------------- scratch (device globals; no allocation) ------------------
// split-bf16 Q/K/V, head-major [b][h][s][d]
__device__ __nv_bfloat16 g_qh[B_*H_*S_*D_];
__device__ __nv_bfloat16 g_ql[B_*H_*S_*D_];
__device__ __nv_bfloat16 g_kh[B_*H_*S_*D_];
__device__ __nv_bfloat16 g_kl[B_*H_*S_*D_];
__device__ __nv_bfloat16 g_vh[B_*H_*S_*D_];
__device__ __nv_bfloat16 g_vl[B_*H_*S_*D_];
// split-bf16 A operand (X first, then attention output)
__device__ __nv_bfloat16 g_ah[B_*S_*DM_];
__device__ __nv_bfloat16 g_al[B_*S_*DM_];
__device__ __nv_bfloat16 g_wh[4*DM_*DM_];     // W^T hi: rows 0..1535 Wq,Wk,Wv; 1536.. Wo
__device__ __nv_bfloat16 g_wl[4*DM_*DM_];     // W^T lo

__device__ __forceinline__ uint32_t smem_u32(const void* p) {
    uint32_t a;
    asm("{ .reg .u64 t; cvta.to.shared.u64 t, %1; cvt.u32.u64 %0, t; }" : "=r"(a) : "l"(p));
    return a;
}

// ---------------- mma.sync building blocks (plain sm_103 PTX) --------------
#define LDSM4(r, addr) \
    asm volatile("ldmatrix.sync.aligned.m8n8.x4.shared.b16 {%0,%1,%2,%3}, [%4];" \
        : "=r"((r)[0]), "=r"((r)[1]), "=r"((r)[2]), "=r"((r)[3]) : "r"(addr))

#define MMA16816(c, a, b0, b1) \
    asm volatile("mma.sync.aligned.m16n8k16.row.col.f32.bf16.bf16.f32 " \
        "{%0,%1,%2,%3}, {%4,%5,%6,%7}, {%8,%9}, {%0,%1,%2,%3};" \
        : "+f"((c)[0]), "+f"((c)[1]), "+f"((c)[2]), "+f"((c)[3]) \
        : "r"((a)[0]), "r"((a)[1]), "r"((a)[2]), "r"((a)[3]), "r"(b0), "r"(b1))

__device__ __forceinline__ void cpa16(uint32_t s, const __nv_bfloat16* g) {
    asm volatile("cp.async.ca.shared.global [%0], [%1], 16;" :: "r"(s), "l"(g));
}

__device__ __forceinline__ void split_bf16(float x, __nv_bfloat16& h, __nv_bfloat16& l) {
    h = __float2bfloat16(x);
    l = __float2bfloat16(x - __bfloat162float(h));
}

// ---------------------------------------------------------------------------
// Conversion kernels
// ---------------------------------------------------------------------------
__global__ void __launch_bounds__(256) conv_split_k(const float* __restrict__ X)
{
    int i = (blockIdx.x * 256 + threadIdx.x) * 4;
    float4 v = *(const float4*)(X + i);
    __nv_bfloat16 h0, h1, h2, h3, l0, l1, l2, l3;
    split_bf16(v.x, h0, l0); split_bf16(v.y, h1, l1);
    split_bf16(v.z, h2, l2); split_bf16(v.w, h3, l3);
    *(__nv_bfloat162*)(g_ah + i)     = __nv_bfloat162(h0, h1);
    *(__nv_bfloat162*)(g_ah + i + 2) = __nv_bfloat162(h2, h3);
    *(__nv_bfloat162*)(g_al + i)     = __nv_bfloat162(l0, l1);
    *(__nv_bfloat162*)(g_al + i + 2) = __nv_bfloat162(l2, l3);
}

__global__ void __launch_bounds__(256) conv_w_k(const float* __restrict__ Wq,
                                                const float* __restrict__ Wk,
                                                const float* __restrict__ Wv,
                                                const float* __restrict__ Wo)
{
    const float* Wsrc = (blockIdx.z == 0) ? Wq : (blockIdx.z == 1 ? Wk :
                        (blockIdx.z == 2 ? Wv : Wo));
    __shared__ float t[32][33];
    int bn = blockIdx.x * 32;
    int bk = blockIdx.y * 32;
    int lx = threadIdx.x & 31, ly = threadIdx.x >> 5;
#pragma unroll
    for (int i = 0; i < 32; i += 8)
        t[ly + i][lx] = Wsrc[(bk + ly + i) * DM_ + bn + lx];
    __syncthreads();
    int rowbase = blockIdx.z * DM_;
#pragma unroll
    for (int i = 0; i < 32; i += 8) {
        int r = ly + i;
        float x = t[lx][r];
        __nv_bfloat16 h, l;
        split_bf16(x, h, l);
        long idx = (long)(rowbase + bn + r) * DM_ + bk + lx;
        g_wh[idx] = h;
        g_wl[idx] = l;
    }
}

// ---------------------------------------------------------------------------
// mma.sync split-bf16 GEMM core (unchanged mainloop).
// ---------------------------------------------------------------------------
#define GSM_BYTES (2 * 40960)

__device__ __forceinline__ void stage(uint32_t sb, int st, int m0, int nbase, int k0)
{
    const int tid = threadIdx.x;
#pragma unroll
    for (int i = 0; i < 2; i++) {
        int u = tid + (i << 8);
        int r = u >> 2, seg = u & 3;
        uint32_t so = sb + st * 40960 + r * 80 + seg * 16;
        long ga = (long)(m0 + r) * DM_ + k0 + seg * 8;
        long gb = (long)(nbase + r) * DM_ + k0 + seg * 8;
        cpa16(so,         g_ah + ga);
        cpa16(so + 10240, g_al + ga);
        cpa16(so + 20480, g_wh + gb);
        cpa16(so + 30720, g_wl + gb);
    }
    asm volatile("cp.async.commit_group;" ::: "memory");
}

__device__ __forceinline__ void compute_chunk(uint32_t sb, int st, float acc[2][8][4])
{
    const int lane = threadIdx.x & 31, w = threadIdx.x >> 5;
    const int wM = (w & 3) * 32, wN = (w >> 2) * 64;
    uint32_t base = sb + st * 40960;
    const int arow = wM + (lane & 15);
    const int achk = (lane >> 4) * 16;
    const int brow = wN + ((lane >> 4) ? 8 : 0) + (lane & 7);
    const int bchk = ((lane >> 3) & 1) * 16;

#pragma unroll
    for (int kk = 0; kk < 2; kk++) {
        const uint32_t kb = kk * 32;
        uint32_t a_hi[2][4], a_lo[2][4];
#pragma unroll
        for (int mt = 0; mt < 2; mt++) {
            uint32_t ad = base + (arow + mt * 16) * 80 + kb + achk;
            LDSM4(a_hi[mt], ad);
            LDSM4(a_lo[mt], ad + 10240);
        }
#pragma unroll
        for (int nb = 0; nb < 4; nb++) {
            uint32_t bd = base + 20480 + (brow + nb * 16) * 80 + kb + bchk;
            uint32_t bh[4], bl[4];
            LDSM4(bh, bd);
            LDSM4(bl, bd + 10240);
#pragma unroll
            for (int mt = 0; mt < 2; mt++) {
                MMA16816(acc[mt][nb * 2 + 0], a_hi[mt], bh[0], bh[1]);
                MMA16816(acc[mt][nb * 2 + 0], a_hi[mt], bl[0], bl[1]);
                MMA16816(acc[mt][nb * 2 + 0], a_lo[mt], bh[0], bh[1]);
                MMA16816(acc[mt][nb * 2 + 1], a_hi[mt], bh[2], bh[3]);
                MMA16816(acc[mt][nb * 2 + 1], a_hi[mt], bl[2], bl[3]);
                MMA16816(acc[mt][nb * 2 + 1], a_lo[mt], bh[2], bh[3]);
            }
        }
    }
}

__device__ __forceinline__ void gemm_mainloop(uint32_t sb, int m0, int nbase,
                                              float acc[2][8][4])
{
#pragma unroll
    for (int mt = 0; mt < 2; mt++)
#pragma unroll
        for (int nf = 0; nf < 8; nf++)
#pragma unroll
            for (int e = 0; e < 4; e++) acc[mt][nf][e] = 0.f;

    stage(sb, 0, m0, nbase, 0);
    for (int c = 0; c < 16; c++) {
        if (c < 15) {
            stage(sb, (c + 1) & 1, m0, nbase, (c + 1) * 32);
            asm volatile("cp.async.wait_group 1;" ::: "memory");
        } else {
            asm volatile("cp.async.wait_group 0;" ::: "memory");
        }
        __syncthreads();
        compute_chunk(sb, c & 1, acc);
        __syncthreads();
    }
}

// QKV projection: head-major scatter of SPLIT-BF16 q/k/v.
__global__ void __launch_bounds__(256, 2) mma_gemm_qkv()
{
    extern __shared__ char sm[];
    uint32_t sb = smem_u32(sm);
    const int m0 = blockIdx.y << 7;
    const int nbase = blockIdx.x << 7;
    float acc[2][8][4];
    gemm_mainloop(sb, m0, nbase, acc);

    const int lane = threadIdx.x & 31, w = threadIdx.x >> 5;
    const int wM = (w & 3) * 32, wN = (w >> 2) * 64;
#pragma unroll
    for (int mt = 0; mt < 2; mt++) {
        int r0 = m0 + wM + mt * 16 + (lane >> 2);
        int b = r0 >> 11, s = r0 & (S_ - 1);
#pragma unroll
        for (int nb = 0; nb < 4; nb++) {
#pragma unroll
            for (int nf = 0; nf < 2; nf++) {
                float* c = acc[mt][nb * 2 + nf];
                int n = nbase + wN + nb * 16 + nf * 8 + (lane & 3) * 2;
                int mat = n >> 9, cc = n & 511;
                int h = cc >> 6, d = cc & 63;
                __nv_bfloat16* oh = (mat == 0) ? g_qh : (mat == 1 ? g_kh : g_vh);
                __nv_bfloat16* ol = (mat == 0) ? g_ql : (mat == 1 ? g_kl : g_vl);
                long o0 = (((long)b * H_ + h) * S_ + s) * D_ + d;
                __nv_bfloat16 h0, h1, h2, h3, l0, l1, l2, l3;
                split_bf16(c[0], h0, l0); split_bf16(c[1], h1, l1);
                split_bf16(c[2], h2, l2); split_bf16(c[3], h3, l3);
                *(__nv_bfloat162*)(oh + o0)          = __nv_bfloat162(h0, h1);
                *(__nv_bfloat162*)(ol + o0)          = __nv_bfloat162(l0, l1);
                *(__nv_bfloat162*)(oh + o0 + 8 * D_) = __nv_bfloat162(h2, h3);
                *(__nv_bfloat162*)(ol + o0 + 8 * D_) = __nv_bfloat162(l2, l3);
            }
        }
    }
}

// Output projection: row-major fp32 store to C.
__global__ void __launch_bounds__(256, 2) mma_gemm_out(float* __restrict__ C)
{
    extern __shared__ char sm[];
    uint32_t sb = smem_u32(sm);
    const int m0 = blockIdx.y << 7;
    const int nbase = blockIdx.x << 7;
    float acc[2][8][4];
    gemm_mainloop(sb, m0, 3 * DM_ + nbase, acc);

    const int lane = threadIdx.x & 31, w = threadIdx.x >> 5;
    const int wM = (w & 3) * 32, wN = (w >> 2) * 64;
#pragma unroll
    for (int mt = 0; mt < 2; mt++) {
        int r0 = m0 + wM + mt * 16 + (lane >> 2);
#pragma unroll
        for (int nb = 0; nb < 4; nb++) {
#pragma unroll
            for (int nf = 0; nf < 2; nf++) {
                float* c = acc[mt][nb * 2 + nf];
                int n = nbase + wN + nb * 16 + nf * 8 + (lane & 3) * 2;
                *(float2*)(C + (long)r0 * DM_ + n)       = make_float2(c[0], c[1]);
                *(float2*)(C + (long)(r0 + 8) * DM_ + n) = make_float2(c[2], c[3]);
            }
        }
    }
}

// ---------------------------------------------------------------------------
// Tensor-core sliding-window attention (split-bf16 mma.sync).
// Block = (64-query tile, head, batch), 256 threads (8 warps, 4m x 2n).
// SMEM (bytes):
//   Qh 0..9216, Ql ..18432           (64 x 72 bf16 rows)
//   Kh 18432..46080, Kl ..73728      (192 x 72)
//   S  fp32 [64][193] aliases 0..49408 (over dead Q/K after phase 1)
//   Vth 73728..99328, Vtl ..124928   (64 x 200, transposed V: [d][j])
//   Ph 124928..150528, Pl ..176128   (64 x 200)
// ---------------------------------------------------------------------------
#define AT_QH   0
#define AT_QL   9216
#define AT_KH   18432
#define AT_KL   46080
#define AT_VTH  73728
#define AT_VTL  99328
#define AT_PH   124928
#define AT_PL   150528
#define AT_BYTES 176128

__global__ void __launch_bounds__(256, 1) attn_k()
{
    extern __shared__ char smc[];
    uint32_t sb = smem_u32(smc);
    float* Ss = (float*)smc;                  // [64][193] alias over Q/K

    const int tid = threadIdx.x;
    const int lane = tid & 31, w = tid >> 5;
    const int s0 = blockIdx.x << 6;
    const int h  = blockIdx.y;
    const int b  = blockIdx.z;
    const long base = ((long)(b * H_ + h) * S_) * D_;

    __nv_bfloat16* Qh = (__nv_bfloat16*)(smc + AT_QH);
    __nv_bfloat16* Ql = (__nv_bfloat16*)(smc + AT_QL);
    __nv_bfloat16* Kh = (__nv_bfloat16*)(smc + AT_KH);
    __nv_bfloat16* Kl = (__nv_bfloat16*)(smc + AT_KL);
    __nv_bfloat16* Vth = (__nv_bfloat16*)(smc + AT_VTH);
    __nv_bfloat16* Vtl = (__nv_bfloat16*)(smc + AT_VTL);
    __nv_bfloat16* Ph = (__nv_bfloat16*)(smc + AT_PH);
    __nv_bfloat16* Pl = (__nv_bfloat16*)(smc + AT_PL);

    // ---- load Q (64x64, rows stride 72) ----
#pragma unroll
    for (int it = 0; it < 2; it++) {
        int idx = tid + it * 256;
        int qq = idx >> 3, dc = (idx & 7) * 8;
        long g = base + (long)(s0 + qq) * D_ + dc;
        *(uint4*)(Qh + qq * 72 + dc) = *(const uint4*)(g_qh + g);
        *(uint4*)(Ql + qq * 72 + dc) = *(const uint4*)(g_ql + g);
    }
    // ---- load K band (192x64) and transposed V (Vt[d][j]) ----
#pragma unroll
    for (int it = 0; it < 6; it++) {
        int idx = tid + it * 256;
        int jr = idx >> 3, dc = (idx & 7) * 8;
        int kg = s0 - (W_ - 1) + jr;
        uint4 kh4 = {0,0,0,0}, kl4 = {0,0,0,0}, vh4 = {0,0,0,0}, vl4 = {0,0,0,0};
        if (kg >= 0) {
            long g = base + (long)kg * D_ + dc;
            kh4 = *(const uint4*)(g_kh + g);
            kl4 = *(const uint4*)(g_kl + g);
            vh4 = *(const uint4*)(g_vh + g);
            vl4 = *(const uint4*)(g_vl + g);
        }
        *(uint4*)(Kh + jr * 72 + dc) = kh4;
        *(uint4*)(Kl + jr * 72 + dc) = kl4;
        const __nv_bfloat16* ve_h = (const __nv_bfloat16*)&vh4;
        const __nv_bfloat16* ve_l = (const __nv_bfloat16*)&vl4;
#pragma unroll
        for (int e = 0; e < 8; e++) {
            Vth[(dc + e) * 200 + jr] = ve_h[e];
            Vtl[(dc + e) * 200 + jr] = ve_l[e];
        }
    }
    __syncthreads();

    // ---- phase 1: S = Q K^T via mma.sync (3-product split) ----
    const int wm = w & 3;          // m-tile (16 rows)
    const int wn = w >> 2;         // n half (96 cols)
    {
        float sacc[12][4];
#pragma unroll
        for (int i = 0; i < 12; i++)
#pragma unroll
            for (int e = 0; e < 4; e++) sacc[i][e] = 0.f;

        const int arow = wm * 16 + (lane & 15);
        const int akoff = (lane >> 4) * 8;
        const int brL = ((lane >> 4) ? 8 : 0) + (lane & 7);
        const int bkoff = ((lane >> 3) & 1) * 8;

#pragma unroll
        for (int ks = 0; ks < 4; ks++) {
            uint32_t aq = sb + AT_QH + (arow * 72 + ks * 16 + akoff) * 2;
            uint32_t a_h[4], a_l[4];
            LDSM4(a_h, aq);
            LDSM4(a_l, aq + (AT_QL - AT_QH));
#pragma unroll
            for (int nb = 0; nb < 6; nb++) {
                int nrow = wn * 96 + nb * 16 + brL;
                uint32_t bk = sb + AT_KH + (nrow * 72 + ks * 16 + bkoff) * 2;
                uint32_t b_h[4], b_l[4];
                LDSM4(b_h, bk);
                LDSM4(b_l, bk + (AT_KL - AT_KH));
                MMA16816(sacc[nb * 2 + 0], a_h, b_h[0], b_h[1]);
                MMA16816(sacc[nb * 2 + 0], a_h, b_l[0], b_l[1]);
                MMA16816(sacc[nb * 2 + 0], a_l, b_h[0], b_h[1]);
                MMA16816(sacc[nb * 2 + 1], a_h, b_h[2], b_h[3]);
                MMA16816(sacc[nb * 2 + 1], a_h, b_l[2], b_l[3]);
                MMA16816(sacc[nb * 2 + 1], a_l, b_h[2], b_h[3]);
            }
        }
        __syncthreads();   // all Q/K reads complete; S may overwrite

        // mask + scale -> S fp32
#pragma unroll
        for (int nb = 0; nb < 6; nb++) {
#pragma unroll
            for (int nf = 0; nf < 2; nf++) {
                float* c = sacc[nb * 2 + nf];
#pragma unroll
                for (int half = 0; half < 2; half++) {
                    int i = wm * 16 + (lane >> 2) + half * 8;
                    int j = wn * 96 + nb * 16 + nf * 8 + (lane & 3) * 2;
                    int lo = (i > (W_ - 1) - s0) ? i : ((W_ - 1) - s0);
                    int hi = i + (W_ - 1);
                    float v0 = c[half * 2 + 0] * 0.125f;
                    float v1 = c[half * 2 + 1] * 0.125f;
                    Ss[i * 193 + j]     = (j     >= lo && j     <= hi) ? v0 : -3.0e38f;
                    Ss[i * 193 + j + 1] = (j + 1 >= lo && j + 1 <= hi) ? v1 : -3.0e38f;
                }
            }
        }
    }
    __syncthreads();

    // ---- phase 2: row softmax (8 warps x 8 rows) ----
    {
#pragma unroll
        for (int rr = 0; rr < 8; rr++) {
            float* row = Ss + ((w << 3) + rr) * 193;
            float m = -3.0e38f;
#pragma unroll
            for (int c = lane; c < 192; c += 32) m = fmaxf(m, row[c]);
#pragma unroll
            for (int msk = 16; msk >= 1; msk >>= 1)
                m = fmaxf(m, __shfl_xor_sync(0xffffffffu, m, msk));
            float ssum = 0.f;
#pragma unroll
            for (int c = lane; c < 192; c += 32) {
                float e = __expf(row[c] - m);
                row[c] = e;
                ssum += e;
            }
#pragma unroll
            for (int msk = 16; msk >= 1; msk >>= 1)
                ssum += __shfl_xor_sync(0xffffffffu, ssum, msk);
            float inv = 1.0f / ssum;
#pragma unroll
            for (int c = lane; c < 192; c += 32) row[c] *= inv;
        }
    }
    __syncthreads();

    // ---- convert P to split-bf16 (rows stride 200) ----
#pragma unroll
    for (int it = 0; it < 6; it++) {
        int idx = tid + it * 256;           // 1536 = 64 rows x 24 col-groups
        int row = idx / 24, cg = (idx % 24) * 8;
        __nv_bfloat16 hh[8], ll[8];
#pragma unroll
        for (int e = 0; e < 8; e++)
            split_bf16(Ss[row * 193 + cg + e], hh[e], ll[e]);
        *(uint4*)(Ph + row * 200 + cg) = *(uint4*)hh;
        *(uint4*)(Pl + row * 200 + cg) = *(uint4*)ll;
    }
    __syncthreads();

    // ---- phase 3: O = P V^T via mma.sync (3-product split) ----
    {
        float oacc[4][4];
#pragma unroll
        for (int i = 0; i < 4; i++)
#pragma unroll
            for (int e = 0; e < 4; e++) oacc[i][e] = 0.f;

        const int arow = wm * 16 + (lane & 15);
        const int akoff = (lane >> 4) * 8;
        const int brL = ((lane >> 4) ? 8 : 0) + (lane & 7);
        const int bkoff = ((lane >> 3) & 1) * 8;

#pragma unroll
        for (int ks = 0; ks < 12; ks++) {
            uint32_t ap = sb + AT_PH + (arow * 200 + ks * 16 + akoff) * 2;
            uint32_t a_h[4], a_l[4];
            LDSM4(a_h, ap);
            LDSM4(a_l, ap + (AT_PL - AT_PH));
#pragma unroll
            for (int nb = 0; nb < 2; nb++) {
                int nrow = wn * 32 + nb * 16 + brL;
                uint32_t bv = sb + AT_VTH + (nrow * 200 + ks * 16 + bkoff) * 2;
                uint32_t b_h[4], b_l[4];
                LDSM4(b_h, bv);
                LDSM4(b_l, bv + (AT_VTL - AT_VTH));
                MMA16816(oacc[nb * 2 + 0], a_h, b_h[0], b_h[1]);
                MMA16816(oacc[nb * 2 + 0], a_h, b_l[0], b_l[1]);
                MMA16816(oacc[nb * 2 + 0], a_l, b_h[0], b_h[1]);
                MMA16816(oacc[nb * 2 + 1], a_h, b_h[2], b_h[3]);
                MMA16816(oacc[nb * 2 + 1], a_h, b_l[2], b_l[3]);
                MMA16816(oacc[nb * 2 + 1], a_l, b_h[2], b_h[3]);
            }
        }

        // epilogue: split-bf16 into g_ah/g_al
#pragma unroll
        for (int nb = 0; nb < 2; nb++) {
#pragma unroll
            for (int nf = 0; nf < 2; nf++) {
                float* c = oacc[nb * 2 + nf];
#pragma unroll
                for (int half = 0; half < 2; half++) {
                    int q = wm * 16 + (lane >> 2) + half * 8;
                    int d = wn * 32 + nb * 16 + nf * 8 + (lane & 3) * 2;
                    long idx = ((long)(b * S_ + s0 + q)) * DM_ + h * D_ + d;
                    __nv_bfloat16 h0, h1, l0, l1;
                    split_bf16(c[half * 2 + 0], h0, l0);
                    split_bf16(c[half * 2 + 1], h1, l1);
                    *(__nv_bfloat162*)(g_ah + idx) = __nv_bfloat162(h0, h1);
                    *(__nv_bfloat162*)(g_al + idx) = __nv_bfloat162(l0, l1);
                }
            }
        }
    }
}

// ---------------------------------------------------------------------------
extern "C" void kernel_launch(void* const* d_in, const int* in_sizes, int n_in,
                              void* d_out, int out_size)
{
    const float* x  = (const float*)d_in[0];
    const float* Wq = (const float*)d_in[1];
    const float* Wk = (const float*)d_in[2];
    const float* Wv = (const float*)d_in[3];
    const float* Wo = (const float*)d_in[4];
    float* out = (float*)d_out;

    cudaFuncSetAttribute(mma_gemm_qkv, cudaFuncAttributeMaxDynamicSharedMemorySize, GSM_BYTES);
    cudaFuncSetAttribute(mma_gemm_out, cudaFuncAttributeMaxDynamicSharedMemorySize, GSM_BYTES);
    cudaFuncSetAttribute(attn_k, cudaFuncAttributeMaxDynamicSharedMemorySize, AT_BYTES);

    conv_split_k<<<(B_*S_*DM_) / 1024, 256>>>(x);
    conv_w_k<<<dim3(16, 16, 4), 256>>>(Wq, Wk, Wv, Wo);
    mma_gemm_qkv<<<dim3(12, 32), 256, GSM_BYTES>>>();
    attn_k<<<dim3(S_ / 64, H_, B_), 256, AT_BYTES>>>();
    mma_gemm_out<<<dim3(4, 32), 256, GSM_BYTES>>>(out);
}

// round 8
// speedup vs baseline: 1.3181x; 1.2149x over previous
#include <cuda_runtime.h>
#include <cuda_bf16.h>
#include <math.h>
#include <stdint.h>

#define B_  2
#define S_  2048
#define H_  8
#define D_  64
#define DM_ 512
#define W_  128

// ---------------- scratch (device globals; no allocation) ------------------
__device__ __nv_bfloat16 g_qh[B_*H_*S_*D_];
__device__ __nv_bfloat16 g_ql[B_*H_*S_*D_];
__device__ __nv_bfloat16 g_kh[B_*H_*S_*D_];
__device__ __nv_bfloat16 g_kl[B_*H_*S_*D_];
__device__ __nv_bfloat16 g_vh[B_*H_*S_*D_];
__device__ __nv_bfloat16 g_vl[B_*H_*S_*D_];
__device__ __nv_bfloat16 g_ah[B_*S_*DM_];
__device__ __nv_bfloat16 g_al[B_*S_*DM_];
__device__ __nv_bfloat16 g_wh[4*DM_*DM_];     // W^T hi: rows 0..1535 Wq,Wk,Wv; 1536.. Wo
__device__ __nv_bfloat16 g_wl[4*DM_*DM_];     // W^T lo

__device__ __forceinline__ uint32_t smem_u32(const void* p) {
    uint32_t a;
    asm("{ .reg .u64 t; cvta.to.shared.u64 t, %1; cvt.u32.u64 %0, t; }" : "=r"(a) : "l"(p));
    return a;
}

// ---------------- mma.sync building blocks (plain sm_103 PTX) --------------
#define LDSM4(r, addr) \
    asm volatile("ldmatrix.sync.aligned.m8n8.x4.shared.b16 {%0,%1,%2,%3}, [%4];" \
        : "=r"((r)[0]), "=r"((r)[1]), "=r"((r)[2]), "=r"((r)[3]) : "r"(addr))

#define LDSM4T(r, addr) \
    asm volatile("ldmatrix.sync.aligned.m8n8.x4.trans.shared.b16 {%0,%1,%2,%3}, [%4];" \
        : "=r"((r)[0]), "=r"((r)[1]), "=r"((r)[2]), "=r"((r)[3]) : "r"(addr))

#define MMA16816(c, a, b0, b1) \
    asm volatile("mma.sync.aligned.m16n8k16.row.col.f32.bf16.bf16.f32 " \
        "{%0,%1,%2,%3}, {%4,%5,%6,%7}, {%8,%9}, {%0,%1,%2,%3};" \
        : "+f"((c)[0]), "+f"((c)[1]), "+f"((c)[2]), "+f"((c)[3]) \
        : "r"((a)[0]), "r"((a)[1]), "r"((a)[2]), "r"((a)[3]), "r"(b0), "r"(b1))

__device__ __forceinline__ void cpa16(uint32_t s, const __nv_bfloat16* g) {
    asm volatile("cp.async.ca.shared.global [%0], [%1], 16;" :: "r"(s), "l"(g));
}
__device__ __forceinline__ void cpa16z(uint32_t s, const __nv_bfloat16* g, uint32_t sz) {
    asm volatile("cp.async.ca.shared.global [%0], [%1], 16, %2;" :: "r"(s), "l"(g), "r"(sz));
}

__device__ __forceinline__ void split_bf16(float x, __nv_bfloat16& h, __nv_bfloat16& l) {
    h = __float2bfloat16(x);
    l = __float2bfloat16(x - __bfloat162float(h));
}
__device__ __forceinline__ uint32_t pkbf(__nv_bfloat16 x, __nv_bfloat16 y) {
    __nv_bfloat162 t(x, y);
    return *(uint32_t*)&t;
}

// ---------------------------------------------------------------------------
// Conversion kernels
// ---------------------------------------------------------------------------
__global__ void __launch_bounds__(256) conv_split_k(const float* __restrict__ X)
{
    int i = (blockIdx.x * 256 + threadIdx.x) * 4;
    float4 v = *(const float4*)(X + i);
    __nv_bfloat16 h0, h1, h2, h3, l0, l1, l2, l3;
    split_bf16(v.x, h0, l0); split_bf16(v.y, h1, l1);
    split_bf16(v.z, h2, l2); split_bf16(v.w, h3, l3);
    *(__nv_bfloat162*)(g_ah + i)     = __nv_bfloat162(h0, h1);
    *(__nv_bfloat162*)(g_ah + i + 2) = __nv_bfloat162(h2, h3);
    *(__nv_bfloat162*)(g_al + i)     = __nv_bfloat162(l0, l1);
    *(__nv_bfloat162*)(g_al + i + 2) = __nv_bfloat162(l2, l3);
}

__global__ void __launch_bounds__(256) conv_w_k(const float* __restrict__ Wq,
                                                const float* __restrict__ Wk,
                                                const float* __restrict__ Wv,
                                                const float* __restrict__ Wo)
{
    const float* Wsrc = (blockIdx.z == 0) ? Wq : (blockIdx.z == 1 ? Wk :
                        (blockIdx.z == 2 ? Wv : Wo));
    __shared__ float t[32][33];
    int bn = blockIdx.x * 32;
    int bk = blockIdx.y * 32;
    int lx = threadIdx.x & 31, ly = threadIdx.x >> 5;
#pragma unroll
    for (int i = 0; i < 32; i += 8)
        t[ly + i][lx] = Wsrc[(bk + ly + i) * DM_ + bn + lx];
    __syncthreads();
    int rowbase = blockIdx.z * DM_;
#pragma unroll
    for (int i = 0; i < 32; i += 8) {
        int r = ly + i;
        float x = t[lx][r];
        __nv_bfloat16 h, l;
        split_bf16(x, h, l);
        long idx = (long)(rowbase + bn + r) * DM_ + bk + lx;
        g_wh[idx] = h;
        g_wl[idx] = l;
    }
}

// ---------------------------------------------------------------------------
// mma.sync split-bf16 GEMM core (unchanged — part of 149.6us best).
// ---------------------------------------------------------------------------
#define GSM_BYTES (2 * 40960)

__device__ __forceinline__ void stage(uint32_t sb, int st, int m0, int nbase, int k0)
{
    const int tid = threadIdx.x;
#pragma unroll
    for (int i = 0; i < 2; i++) {
        int u = tid + (i << 8);
        int r = u >> 2, seg = u & 3;
        uint32_t so = sb + st * 40960 + r * 80 + seg * 16;
        long ga = (long)(m0 + r) * DM_ + k0 + seg * 8;
        long gb = (long)(nbase + r) * DM_ + k0 + seg * 8;
        cpa16(so,         g_ah + ga);
        cpa16(so + 10240, g_al + ga);
        cpa16(so + 20480, g_wh + gb);
        cpa16(so + 30720, g_wl + gb);
    }
    asm volatile("cp.async.commit_group;" ::: "memory");
}

__device__ __forceinline__ void compute_chunk(uint32_t sb, int st, float acc[2][8][4])
{
    const int lane = threadIdx.x & 31, w = threadIdx.x >> 5;
    const int wM = (w & 3) * 32, wN = (w >> 2) * 64;
    uint32_t base = sb + st * 40960;
    const int arow = wM + (lane & 15);
    const int achk = (lane >> 4) * 16;
    const int brow = wN + ((lane >> 4) ? 8 : 0) + (lane & 7);
    const int bchk = ((lane >> 3) & 1) * 16;

#pragma unroll
    for (int kk = 0; kk < 2; kk++) {
        const uint32_t kb = kk * 32;
        uint32_t a_hi[2][4], a_lo[2][4];
#pragma unroll
        for (int mt = 0; mt < 2; mt++) {
            uint32_t ad = base + (arow + mt * 16) * 80 + kb + achk;
            LDSM4(a_hi[mt], ad);
            LDSM4(a_lo[mt], ad + 10240);
        }
#pragma unroll
        for (int nb = 0; nb < 4; nb++) {
            uint32_t bd = base + 20480 + (brow + nb * 16) * 80 + kb + bchk;
            uint32_t bh[4], bl[4];
            LDSM4(bh, bd);
            LDSM4(bl, bd + 10240);
#pragma unroll
            for (int mt = 0; mt < 2; mt++) {
                MMA16816(acc[mt][nb * 2 + 0], a_hi[mt], bh[0], bh[1]);
                MMA16816(acc[mt][nb * 2 + 0], a_hi[mt], bl[0], bl[1]);
                MMA16816(acc[mt][nb * 2 + 0], a_lo[mt], bh[0], bh[1]);
                MMA16816(acc[mt][nb * 2 + 1], a_hi[mt], bh[2], bh[3]);
                MMA16816(acc[mt][nb * 2 + 1], a_hi[mt], bl[2], bl[3]);
                MMA16816(acc[mt][nb * 2 + 1], a_lo[mt], bh[2], bh[3]);
            }
        }
    }
}

__device__ __forceinline__ void gemm_mainloop(uint32_t sb, int m0, int nbase,
                                              float acc[2][8][4])
{
#pragma unroll
    for (int mt = 0; mt < 2; mt++)
#pragma unroll
        for (int nf = 0; nf < 8; nf++)
#pragma unroll
            for (int e = 0; e < 4; e++) acc[mt][nf][e] = 0.f;

    stage(sb, 0, m0, nbase, 0);
    for (int c = 0; c < 16; c++) {
        if (c < 15) {
            stage(sb, (c + 1) & 1, m0, nbase, (c + 1) * 32);
            asm volatile("cp.async.wait_group 1;" ::: "memory");
        } else {
            asm volatile("cp.async.wait_group 0;" ::: "memory");
        }
        __syncthreads();
        compute_chunk(sb, c & 1, acc);
        __syncthreads();
    }
}

__global__ void __launch_bounds__(256, 2) mma_gemm_qkv()
{
    extern __shared__ char sm[];
    uint32_t sb = smem_u32(sm);
    const int m0 = blockIdx.y << 7;
    const int nbase = blockIdx.x << 7;
    float acc[2][8][4];
    gemm_mainloop(sb, m0, nbase, acc);

    const int lane = threadIdx.x & 31, w = threadIdx.x >> 5;
    const int wM = (w & 3) * 32, wN = (w >> 2) * 64;
#pragma unroll
    for (int mt = 0; mt < 2; mt++) {
        int r0 = m0 + wM + mt * 16 + (lane >> 2);
        int b = r0 >> 11, s = r0 & (S_ - 1);
#pragma unroll
        for (int nb = 0; nb < 4; nb++) {
#pragma unroll
            for (int nf = 0; nf < 2; nf++) {
                float* c = acc[mt][nb * 2 + nf];
                int n = nbase + wN + nb * 16 + nf * 8 + (lane & 3) * 2;
                int mat = n >> 9, cc = n & 511;
                int h = cc >> 6, d = cc & 63;
                __nv_bfloat16* oh = (mat == 0) ? g_qh : (mat == 1 ? g_kh : g_vh);
                __nv_bfloat16* ol = (mat == 0) ? g_ql : (mat == 1 ? g_kl : g_vl);
                long o0 = (((long)b * H_ + h) * S_ + s) * D_ + d;
                __nv_bfloat16 h0, h1, h2, h3, l0, l1, l2, l3;
                split_bf16(c[0], h0, l0); split_bf16(c[1], h1, l1);
                split_bf16(c[2], h2, l2); split_bf16(c[3], h3, l3);
                *(__nv_bfloat162*)(oh + o0)          = __nv_bfloat162(h0, h1);
                *(__nv_bfloat162*)(ol + o0)          = __nv_bfloat162(l0, l1);
                *(__nv_bfloat162*)(oh + o0 + 8 * D_) = __nv_bfloat162(h2, h3);
                *(__nv_bfloat162*)(ol + o0 + 8 * D_) = __nv_bfloat162(l2, l3);
            }
        }
    }
}

__global__ void __launch_bounds__(256, 2) mma_gemm_out(float* __restrict__ C)
{
    extern __shared__ char sm[];
    uint32_t sb = smem_u32(sm);
    const int m0 = blockIdx.y << 7;
    const int nbase = blockIdx.x << 7;
    float acc[2][8][4];
    gemm_mainloop(sb, m0, 3 * DM_ + nbase, acc);

    const int lane = threadIdx.x & 31, w = threadIdx.x >> 5;
    const int wM = (w & 3) * 32, wN = (w >> 2) * 64;
#pragma unroll
    for (int mt = 0; mt < 2; mt++) {
        int r0 = m0 + wM + mt * 16 + (lane >> 2);
#pragma unroll
        for (int nb = 0; nb < 4; nb++) {
#pragma unroll
            for (int nf = 0; nf < 2; nf++) {
                float* c = acc[mt][nb * 2 + nf];
                int n = nbase + wN + nb * 16 + nf * 8 + (lane & 3) * 2;
                *(float2*)(C + (long)r0 * DM_ + n)       = make_float2(c[0], c[1]);
                *(float2*)(C + (long)(r0 + 8) * DM_ + n) = make_float2(c[2], c[3]);
            }
        }
    }
}

// ---------------------------------------------------------------------------
// Flash-style tensor-core sliding-window attention.
// 256 threads (8 warps): wm = w&3 (16-row m-tile), wn = w>>2 (96-key half).
// P kept in registers (S accumulator fragments reinterpreted as A fragments).
// V loaded natural [j][d]; B fragments via ldmatrix.x4.trans.
// SMEM: Qh 0 | Ql 9216 | Kh 18432 | Kl 46080 | Vh 73728 | Vl 101376
//       | Red 129024 (1KB).  Obuf (2x 64x66 fp32) aliases dead Q/K at 0.
// ---------------------------------------------------------------------------
#define AT_QH   0
#define AT_QL   9216
#define AT_KH   18432
#define AT_KL   46080
#define AT_VH   73728
#define AT_VL   101376
#define AT_RED  129024
#define AT_BYTES 130048

__global__ void __launch_bounds__(256, 1) attn_k()
{
    extern __shared__ char smc[];
    uint32_t sb = smem_u32(smc);

    const int tid = threadIdx.x;
    const int lane = tid & 31, w = tid >> 5;
    const int wm = w & 3, wn = w >> 2;
    const int s0 = blockIdx.x << 6;
    const int h  = blockIdx.y;
    const int b  = blockIdx.z;
    const long base = ((long)(b * H_ + h) * S_) * D_;

    // ---- async loads: Q (64x64), K/V bands (192x64), rows stride 72 -------
#pragma unroll
    for (int it = 0; it < 2; it++) {
        int idx = tid + it * 256;
        int row = idx >> 3, dc = (idx & 7) * 8;
        uint32_t so = sb + AT_QH + row * 144 + dc * 2;
        long g = base + (long)(s0 + row) * D_ + dc;
        cpa16(so, g_qh + g);
        cpa16(so + (AT_QL - AT_QH), g_ql + g);
    }
#pragma unroll
    for (int it = 0; it < 6; it++) {
        int idx = tid + it * 256;
        int jr = idx >> 3, dc = (idx & 7) * 8;
        int kg = s0 - (W_ - 1) + jr;
        uint32_t ok = (kg >= 0) ? 16u : 0u;
        long g = base + (long)(kg >= 0 ? kg : 0) * D_ + dc;
        uint32_t sk = sb + AT_KH + jr * 144 + dc * 2;
        cpa16z(sk,         g_kh + g, ok);
        cpa16z(sk + 27648, g_kl + g, ok);
        uint32_t sv = sb + AT_VH + jr * 144 + dc * 2;
        cpa16z(sv,         g_vh + g, ok);
        cpa16z(sv + 27648, g_vl + g, ok);
    }
    asm volatile("cp.async.commit_group;" ::: "memory");
    asm volatile("cp.async.wait_group 0;" ::: "memory");
    __syncthreads();

    // ---- phase 1: S = Q K^T, fragments in registers -----------------------
    float sacc[12][4];
#pragma unroll
    for (int i = 0; i < 12; i++)
#pragma unroll
        for (int e = 0; e < 4; e++) sacc[i][e] = 0.f;

    {
        const int arow = wm * 16 + (lane & 15);
        const int akoff = (lane >> 4) * 8;
        const int brL = ((lane >> 4) ? 8 : 0) + (lane & 7);
        const int bkoff = ((lane >> 3) & 1) * 8;
#pragma unroll
        for (int ks = 0; ks < 4; ks++) {
            uint32_t aq = sb + AT_QH + (arow * 72 + ks * 16 + akoff) * 2;
            uint32_t a_h[4], a_l[4];
            LDSM4(a_h, aq);
            LDSM4(a_l, aq + (AT_QL - AT_QH));
#pragma unroll
            for (int nb = 0; nb < 6; nb++) {
                int nrow = wn * 96 + nb * 16 + brL;
                uint32_t bk = sb + AT_KH + (nrow * 72 + ks * 16 + bkoff) * 2;
                uint32_t b_h[4], b_l[4];
                LDSM4(b_h, bk);
                LDSM4(b_l, bk + 27648);
                MMA16816(sacc[nb * 2 + 0], a_h, b_h[0], b_h[1]);
                MMA16816(sacc[nb * 2 + 0], a_h, b_l[0], b_l[1]);
                MMA16816(sacc[nb * 2 + 0], a_l, b_h[0], b_h[1]);
                MMA16816(sacc[nb * 2 + 1], a_h, b_h[2], b_h[3]);
                MMA16816(sacc[nb * 2 + 1], a_h, b_l[2], b_l[3]);
                MMA16816(sacc[nb * 2 + 1], a_l, b_h[2], b_h[3]);
            }
        }
    }

    // ---- mask + scale in registers ----------------------------------------
    const int i_t = wm * 16 + (lane >> 2);
    const int i_b = i_t + 8;
    const int lo_t = (i_t > (W_ - 1) - s0) ? i_t : ((W_ - 1) - s0);
    const int hi_t = i_t + (W_ - 1);
    const int lo_b = (i_b > (W_ - 1) - s0) ? i_b : ((W_ - 1) - s0);
    const int hi_b = i_b + (W_ - 1);
#pragma unroll
    for (int t = 0; t < 12; t++) {
        int j0 = wn * 96 + t * 8 + (lane & 3) * 2;
        float* c = sacc[t];
        c[0] = (j0     >= lo_t && j0     <= hi_t) ? c[0] * 0.125f : -3.0e38f;
        c[1] = (j0 + 1 >= lo_t && j0 + 1 <= hi_t) ? c[1] * 0.125f : -3.0e38f;
        c[2] = (j0     >= lo_b && j0     <= hi_b) ? c[2] * 0.125f : -3.0e38f;
        c[3] = (j0 + 1 >= lo_b && j0 + 1 <= hi_b) ? c[3] * 0.125f : -3.0e38f;
    }

    // ---- register softmax with cross-warp reduction -----------------------
    float* Red = (float*)(smc + AT_RED);     // [0..127]=max, [128..255]=sum
    float mt = -3.0e38f, mb = -3.0e38f;
#pragma unroll
    for (int t = 0; t < 12; t++) {
        mt = fmaxf(mt, fmaxf(sacc[t][0], sacc[t][1]));
        mb = fmaxf(mb, fmaxf(sacc[t][2], sacc[t][3]));
    }
    mt = fmaxf(mt, __shfl_xor_sync(0xffffffffu, mt, 1));
    mt = fmaxf(mt, __shfl_xor_sync(0xffffffffu, mt, 2));
    mb = fmaxf(mb, __shfl_xor_sync(0xffffffffu, mb, 1));
    mb = fmaxf(mb, __shfl_xor_sync(0xffffffffu, mb, 2));
    if ((lane & 3) == 0) {
        Red[wn * 64 + i_t] = mt;
        Red[wn * 64 + i_b] = mb;
    }
    __syncthreads();
    const float Mt = fmaxf(Red[i_t], Red[64 + i_t]);
    const float Mb = fmaxf(Red[i_b], Red[64 + i_b]);

    float st = 0.f, sbt = 0.f;
#pragma unroll
    for (int t = 0; t < 12; t++) {
        float* c = sacc[t];
        c[0] = __expf(c[0] - Mt);
        c[1] = __expf(c[1] - Mt);
        c[2] = __expf(c[2] - Mb);
        c[3] = __expf(c[3] - Mb);
        st  += c[0] + c[1];
        sbt += c[2] + c[3];
    }
    st  += __shfl_xor_sync(0xffffffffu, st, 1);
    st  += __shfl_xor_sync(0xffffffffu, st, 2);
    sbt += __shfl_xor_sync(0xffffffffu, sbt, 1);
    sbt += __shfl_xor_sync(0xffffffffu, sbt, 2);
    if ((lane & 3) == 0) {
        Red[128 + wn * 64 + i_t] = st;
        Red[128 + wn * 64 + i_b] = sbt;
    }
    __syncthreads();
    const float inv_t = 1.0f / (Red[128 + i_t] + Red[192 + i_t]);
    const float inv_b = 1.0f / (Red[128 + i_b] + Red[192 + i_b]);

    // ---- convert P fragments to split-bf16 A fragments (registers) --------
    uint32_t pah[6][4], pal[6][4];
#pragma unroll
    for (int ks = 0; ks < 6; ks++) {
        float* c0 = sacc[2 * ks];
        float* c1 = sacc[2 * ks + 1];
        __nv_bfloat16 h00, h01, h02, h03, h10, h11, h12, h13;
        __nv_bfloat16 l00, l01, l02, l03, l10, l11, l12, l13;
        split_bf16(c0[0] * inv_t, h00, l00);
        split_bf16(c0[1] * inv_t, h01, l01);
        split_bf16(c0[2] * inv_b, h02, l02);
        split_bf16(c0[3] * inv_b, h03, l03);
        split_bf16(c1[0] * inv_t, h10, l10);
        split_bf16(c1[1] * inv_t, h11, l11);
        split_bf16(c1[2] * inv_b, h12, l12);
        split_bf16(c1[3] * inv_b, h13, l13);
        pah[ks][0] = pkbf(h00, h01); pah[ks][1] = pkbf(h02, h03);
        pah[ks][2] = pkbf(h10, h11); pah[ks][3] = pkbf(h12, h13);
        pal[ks][0] = pkbf(l00, l01); pal[ks][1] = pkbf(l02, l03);
        pal[ks][2] = pkbf(l10, l11); pal[ks][3] = pkbf(l12, l13);
    }

    // ---- phase 3: partial O = P_half * V_half (ldmatrix.trans B) ----------
    float oacc[8][4];
#pragma unroll
    for (int i = 0; i < 8; i++)
#pragma unroll
        for (int e = 0; e < 4; e++) oacc[i][e] = 0.f;

    {
        const int jrow = wn * 96 + (lane & 15);
        const int dsel = (lane >> 4) * 8;
#pragma unroll
        for (int ks = 0; ks < 6; ks++) {
#pragma unroll
            for (int db = 0; db < 4; db++) {
                uint32_t bv = sb + AT_VH + ((jrow + ks * 16) * 72 + db * 16 + dsel) * 2;
                uint32_t b_h[4], b_l[4];
                LDSM4T(b_h, bv);
                LDSM4T(b_l, bv + 27648);
                MMA16816(oacc[db * 2 + 0], pah[ks], b_h[0], b_h[1]);
                MMA16816(oacc[db * 2 + 0], pah[ks], b_l[0], b_l[1]);
                MMA16816(oacc[db * 2 + 0], pal[ks], b_h[0], b_h[1]);
                MMA16816(oacc[db * 2 + 1], pah[ks], b_h[2], b_h[3]);
                MMA16816(oacc[db * 2 + 1], pah[ks], b_l[2], b_l[3]);
                MMA16816(oacc[db * 2 + 1], pal[ks], b_h[2], b_h[3]);
            }
        }
    }

    // ---- combine the two wn-half partials via smem (aliases dead Q/K) -----
    float* Obuf = (float*)smc + wn * (64 * 66);
#pragma unroll
    for (int t = 0; t < 8; t++) {
        int d = t * 8 + (lane & 3) * 2;
        *(float2*)(Obuf + i_t * 66 + d) = make_float2(oacc[t][0], oacc[t][1]);
        *(float2*)(Obuf + i_b * 66 + d) = make_float2(oacc[t][2], oacc[t][3]);
    }
    __syncthreads();

    float* Ob0 = (float*)smc;
    float* Ob1 = (float*)smc + 64 * 66;
#pragma unroll
    for (int it = 0; it < 2; it++) {
        int idx = tid + it * 256;
        int row = idx >> 3, dg = (idx & 7) * 8;
        __nv_bfloat16 hh[8], ll[8];
#pragma unroll
        for (int e = 0; e < 8; e++) {
            float v = Ob0[row * 66 + dg + e] + Ob1[row * 66 + dg + e];
            split_bf16(v, hh[e], ll[e]);
        }
        long gidx = ((long)(b * S_ + s0 + row)) * DM_ + h * D_ + dg;
        *(uint4*)(g_ah + gidx) = *(uint4*)hh;
        *(uint4*)(g_al + gidx) = *(uint4*)ll;
    }
}

// ---------------------------------------------------------------------------
extern "C" void kernel_launch(void* const* d_in, const int* in_sizes, int n_in,
                              void* d_out, int out_size)
{
    const float* x  = (const float*)d_in[0];
    const float* Wq = (const float*)d_in[1];
    const float* Wk = (const float*)d_in[2];
    const float* Wv = (const float*)d_in[3];
    const float* Wo = (const float*)d_in[4];
    float* out = (float*)d_out;

    cudaFuncSetAttribute(mma_gemm_qkv, cudaFuncAttributeMaxDynamicSharedMemorySize, GSM_BYTES);
    cudaFuncSetAttribute(mma_gemm_out, cudaFuncAttributeMaxDynamicSharedMemorySize, GSM_BYTES);
    cudaFuncSetAttribute(attn_k, cudaFuncAttributeMaxDynamicSharedMemorySize, AT_BYTES);

    conv_split_k<<<(B_*S_*DM_) / 1024, 256>>>(x);
    conv_w_k<<<dim3(16, 16, 4), 256>>>(Wq, Wk, Wv, Wo);
    mma_gemm_qkv<<<dim3(12, 32), 256, GSM_BYTES>>>();
    attn_k<<<dim3(S_ / 64, H_, B_), 256, AT_BYTES>>>();
    mma_gemm_out<<<dim3(4, 32), 256, GSM_BYTES>>>(out);
}

// round 9
// speedup vs baseline: 1.4583x; 1.1064x over previous
#include <cuda_runtime.h>
#include <cuda_bf16.h>
#include <math.h>
#include <stdint.h>

#define B_  2
#define S_  2048
#define H_  8
#define D_  64
#define DM_ 512
#define W_  128

// ---------------- scratch (device globals; no allocation) ------------------
__device__ __nv_bfloat16 g_qh[B_*H_*S_*D_];
__device__ __nv_bfloat16 g_ql[B_*H_*S_*D_];
__device__ __nv_bfloat16 g_kh[B_*H_*S_*D_];
__device__ __nv_bfloat16 g_kl[B_*H_*S_*D_];
__device__ __nv_bfloat16 g_vh[B_*H_*S_*D_];
__device__ __nv_bfloat16 g_vl[B_*H_*S_*D_];
__device__ __nv_bfloat16 g_ah[B_*S_*DM_];
__device__ __nv_bfloat16 g_al[B_*S_*DM_];
__device__ __nv_bfloat16 g_wh[4*DM_*DM_];     // W^T hi: rows 0..1535 Wq,Wk,Wv; 1536.. Wo
__device__ __nv_bfloat16 g_wl[4*DM_*DM_];     // W^T lo

__device__ __forceinline__ uint32_t smem_u32(const void* p) {
    uint32_t a;
    asm("{ .reg .u64 t; cvta.to.shared.u64 t, %1; cvt.u32.u64 %0, t; }" : "=r"(a) : "l"(p));
    return a;
}

// ---------------- mma.sync building blocks (plain sm_103 PTX) --------------
#define LDSM4(r, addr) \
    asm volatile("ldmatrix.sync.aligned.m8n8.x4.shared.b16 {%0,%1,%2,%3}, [%4];" \
        : "=r"((r)[0]), "=r"((r)[1]), "=r"((r)[2]), "=r"((r)[3]) : "r"(addr))

#define LDSM4T(r, addr) \
    asm volatile("ldmatrix.sync.aligned.m8n8.x4.trans.shared.b16 {%0,%1,%2,%3}, [%4];" \
        : "=r"((r)[0]), "=r"((r)[1]), "=r"((r)[2]), "=r"((r)[3]) : "r"(addr))

#define MMA16816(c, a, b0, b1) \
    asm volatile("mma.sync.aligned.m16n8k16.row.col.f32.bf16.bf16.f32 " \
        "{%0,%1,%2,%3}, {%4,%5,%6,%7}, {%8,%9}, {%0,%1,%2,%3};" \
        : "+f"((c)[0]), "+f"((c)[1]), "+f"((c)[2]), "+f"((c)[3]) \
        : "r"((a)[0]), "r"((a)[1]), "r"((a)[2]), "r"((a)[3]), "r"(b0), "r"(b1))

__device__ __forceinline__ void cpa16(uint32_t s, const __nv_bfloat16* g) {
    asm volatile("cp.async.ca.shared.global [%0], [%1], 16;" :: "r"(s), "l"(g));
}
__device__ __forceinline__ void cpa16z(uint32_t s, const __nv_bfloat16* g, uint32_t sz) {
    asm volatile("cp.async.ca.shared.global [%0], [%1], 16, %2;" :: "r"(s), "l"(g), "r"(sz));
}

__device__ __forceinline__ void split_bf16(float x, __nv_bfloat16& h, __nv_bfloat16& l) {
    h = __float2bfloat16(x);
    l = __float2bfloat16(x - __bfloat162float(h));
}
__device__ __forceinline__ uint32_t pkbf(__nv_bfloat16 x, __nv_bfloat16 y) {
    __nv_bfloat162 t(x, y);
    return *(uint32_t*)&t;
}

// ---------------------------------------------------------------------------
// Merged conversion kernel: blocks [0,2048) split X; [2048,3072) split+T W.
// ---------------------------------------------------------------------------
__global__ void __launch_bounds__(256) conv_k(const float* __restrict__ X,
                                              const float* __restrict__ Wq,
                                              const float* __restrict__ Wk,
                                              const float* __restrict__ Wv,
                                              const float* __restrict__ Wo)
{
    __shared__ float t[32][33];
    if (blockIdx.x < 2048) {
        int i = (blockIdx.x * 256 + threadIdx.x) * 4;
        float4 v = *(const float4*)(X + i);
        __nv_bfloat16 h0, h1, h2, h3, l0, l1, l2, l3;
        split_bf16(v.x, h0, l0); split_bf16(v.y, h1, l1);
        split_bf16(v.z, h2, l2); split_bf16(v.w, h3, l3);
        *(__nv_bfloat162*)(g_ah + i)     = __nv_bfloat162(h0, h1);
        *(__nv_bfloat162*)(g_ah + i + 2) = __nv_bfloat162(h2, h3);
        *(__nv_bfloat162*)(g_al + i)     = __nv_bfloat162(l0, l1);
        *(__nv_bfloat162*)(g_al + i + 2) = __nv_bfloat162(l2, l3);
        return;
    }
    int wi = blockIdx.x - 2048;
    int z  = wi >> 8;
    int bn = (wi & 15) * 32;
    int bk = ((wi >> 4) & 15) * 32;
    const float* Wsrc = (z == 0) ? Wq : (z == 1 ? Wk : (z == 2 ? Wv : Wo));
    int lx = threadIdx.x & 31, ly = threadIdx.x >> 5;
#pragma unroll
    for (int i = 0; i < 32; i += 8)
        t[ly + i][lx] = Wsrc[(bk + ly + i) * DM_ + bn + lx];
    __syncthreads();
    int rowbase = z * DM_;
#pragma unroll
    for (int i = 0; i < 32; i += 8) {
        int r = ly + i;
        float x = t[lx][r];
        __nv_bfloat16 h, l;
        split_bf16(x, h, l);
        long idx = (long)(rowbase + bn + r) * DM_ + bk + lx;
        g_wh[idx] = h;
        g_wl[idx] = l;
    }
}

// ---------------------------------------------------------------------------
// mma.sync split-bf16 GEMM: 3-stage cp.async pipeline, single sync per chunk.
// Stage (32KB): Ah[128][32sw] | Al | Bh | Bl, swizzled 64B rows:
//   chunk' = (chunk + (row>>1)) & 3   (conflict-free for stores + ldmatrix)
// ---------------------------------------------------------------------------
#define GSTAGE 32768
#define GSM_BYTES (3 * GSTAGE)

__device__ __forceinline__ void stage(uint32_t sb, int st, int m0, int nbase, int k0)
{
    const int tid = threadIdx.x;
#pragma unroll
    for (int i = 0; i < 2; i++) {
        int u = tid + (i << 8);
        int r = u >> 2, seg = u & 3;
        int sw = ((seg + (r >> 1)) & 3) * 16;
        uint32_t so = sb + st * GSTAGE + r * 64 + sw;
        long ga = (long)(m0 + r) * DM_ + k0 + seg * 8;
        long gb = (long)(nbase + r) * DM_ + k0 + seg * 8;
        cpa16(so,         g_ah + ga);
        cpa16(so + 8192,  g_al + ga);
        cpa16(so + 16384, g_wh + gb);
        cpa16(so + 24576, g_wl + gb);
    }
    asm volatile("cp.async.commit_group;" ::: "memory");
}

__device__ __forceinline__ void compute_chunk(uint32_t sb, int st, float acc[2][8][4])
{
    const int lane = threadIdx.x & 31, w = threadIdx.x >> 5;
    const int wM = (w & 3) * 32, wN = (w >> 2) * 64;
    uint32_t base = sb + st * GSTAGE;
    const int arow_ = wM + (lane & 15);
    const int ach = lane >> 4;                 // 0/1
    const int brow_ = wN + ((lane >> 4) ? 8 : 0) + (lane & 7);
    const int bch = (lane >> 3) & 1;

#pragma unroll
    for (int kk = 0; kk < 2; kk++) {
        uint32_t a_hi[2][4], a_lo[2][4];
#pragma unroll
        for (int mt = 0; mt < 2; mt++) {
            int row = arow_ + mt * 16;
            int ch = ((kk * 2 + ach + (row >> 1)) & 3) * 16;
            uint32_t ad = base + row * 64 + ch;
            LDSM4(a_hi[mt], ad);
            LDSM4(a_lo[mt], ad + 8192);
        }
#pragma unroll
        for (int nb = 0; nb < 4; nb++) {
            int row = brow_ + nb * 16;
            int ch = ((kk * 2 + bch + (row >> 1)) & 3) * 16;
            uint32_t bd = base + 16384 + row * 64 + ch;
            uint32_t bh[4], bl[4];
            LDSM4(bh, bd);
            LDSM4(bl, bd + 8192);
#pragma unroll
            for (int mt = 0; mt < 2; mt++) {
                MMA16816(acc[mt][nb * 2 + 0], a_hi[mt], bh[0], bh[1]);
                MMA16816(acc[mt][nb * 2 + 0], a_hi[mt], bl[0], bl[1]);
                MMA16816(acc[mt][nb * 2 + 0], a_lo[mt], bh[0], bh[1]);
                MMA16816(acc[mt][nb * 2 + 1], a_hi[mt], bh[2], bh[3]);
                MMA16816(acc[mt][nb * 2 + 1], a_hi[mt], bl[2], bl[3]);
                MMA16816(acc[mt][nb * 2 + 1], a_lo[mt], bh[2], bh[3]);
            }
        }
    }
}

__device__ __forceinline__ void gemm_mainloop(uint32_t sb, int m0, int nbase,
                                              float acc[2][8][4])
{
#pragma unroll
    for (int mt = 0; mt < 2; mt++)
#pragma unroll
        for (int nf = 0; nf < 8; nf++)
#pragma unroll
            for (int e = 0; e < 4; e++) acc[mt][nf][e] = 0.f;

    stage(sb, 0, m0, nbase, 0);
    stage(sb, 1, m0, nbase, 32);
    for (int c = 0; c < 16; c++) {
        if (c < 15) asm volatile("cp.async.wait_group 1;" ::: "memory");
        else        asm volatile("cp.async.wait_group 0;" ::: "memory");
        __syncthreads();
        compute_chunk(sb, c % 3, acc);
        if (c < 14) stage(sb, (c + 2) % 3, m0, nbase, (c + 2) * 32);
    }
}

__global__ void __launch_bounds__(256, 2) mma_gemm_qkv()
{
    extern __shared__ char sm[];
    uint32_t sb = smem_u32(sm);
    const int m0 = blockIdx.y << 7;
    const int nbase = blockIdx.x << 7;
    float acc[2][8][4];
    gemm_mainloop(sb, m0, nbase, acc);

    const int lane = threadIdx.x & 31, w = threadIdx.x >> 5;
    const int wM = (w & 3) * 32, wN = (w >> 2) * 64;
#pragma unroll
    for (int mt = 0; mt < 2; mt++) {
        int r0 = m0 + wM + mt * 16 + (lane >> 2);
        int b = r0 >> 11, s = r0 & (S_ - 1);
#pragma unroll
        for (int nb = 0; nb < 4; nb++) {
#pragma unroll
            for (int nf = 0; nf < 2; nf++) {
                float* c = acc[mt][nb * 2 + nf];
                int n = nbase + wN + nb * 16 + nf * 8 + (lane & 3) * 2;
                int mat = n >> 9, cc = n & 511;
                int h = cc >> 6, d = cc & 63;
                __nv_bfloat16* oh = (mat == 0) ? g_qh : (mat == 1 ? g_kh : g_vh);
                __nv_bfloat16* ol = (mat == 0) ? g_ql : (mat == 1 ? g_kl : g_vl);
                long o0 = (((long)b * H_ + h) * S_ + s) * D_ + d;
                __nv_bfloat16 h0, h1, h2, h3, l0, l1, l2, l3;
                split_bf16(c[0], h0, l0); split_bf16(c[1], h1, l1);
                split_bf16(c[2], h2, l2); split_bf16(c[3], h3, l3);
                *(__nv_bfloat162*)(oh + o0)          = __nv_bfloat162(h0, h1);
                *(__nv_bfloat162*)(ol + o0)          = __nv_bfloat162(l0, l1);
                *(__nv_bfloat162*)(oh + o0 + 8 * D_) = __nv_bfloat162(h2, h3);
                *(__nv_bfloat162*)(ol + o0 + 8 * D_) = __nv_bfloat162(l2, l3);
            }
        }
    }
}

__global__ void __launch_bounds__(256, 2) mma_gemm_out(float* __restrict__ C)
{
    extern __shared__ char sm[];
    uint32_t sb = smem_u32(sm);
    const int m0 = blockIdx.y << 7;
    const int nbase = blockIdx.x << 7;
    float acc[2][8][4];
    gemm_mainloop(sb, m0, 3 * DM_ + nbase, acc);

    const int lane = threadIdx.x & 31, w = threadIdx.x >> 5;
    const int wM = (w & 3) * 32, wN = (w >> 2) * 64;
#pragma unroll
    for (int mt = 0; mt < 2; mt++) {
        int r0 = m0 + wM + mt * 16 + (lane >> 2);
#pragma unroll
        for (int nb = 0; nb < 4; nb++) {
#pragma unroll
            for (int nf = 0; nf < 2; nf++) {
                float* c = acc[mt][nb * 2 + nf];
                int n = nbase + wN + nb * 16 + nf * 8 + (lane & 3) * 2;
                *(float2*)(C + (long)r0 * DM_ + n)       = make_float2(c[0], c[1]);
                *(float2*)(C + (long)(r0 + 8) * DM_ + n) = make_float2(c[2], c[3]);
            }
        }
    }
}

// ---------------------------------------------------------------------------
// Flash-style tensor-core sliding-window attention, 2 CTAs/SM.
// V is loaded AFTER phase 1 into K's dead smem (arrival hidden by softmax).
// SMEM: Qh 0 | Ql 9216 | Kh/Vh 18432 | Kl/Vl 46080 | Red 73728. 74752 B.
// Obuf (2 x 64x66 fp32 = 33792 B) aliases dead Q + V-head after a barrier.
// ---------------------------------------------------------------------------
#define AT_QH   0
#define AT_QL   9216
#define AT_KH   18432
#define AT_KL   46080
#define AT_VH   18432
#define AT_VL   46080
#define AT_RED  73728
#define AT_BYTES 74752

__global__ void __launch_bounds__(256, 2) attn_k()
{
    extern __shared__ char smc[];
    uint32_t sb = smem_u32(smc);

    const int tid = threadIdx.x;
    const int lane = tid & 31, w = tid >> 5;
    const int wm = w & 3, wn = w >> 2;
    const int s0 = blockIdx.x << 6;
    const int h  = blockIdx.y;
    const int b  = blockIdx.z;
    const long base = ((long)(b * H_ + h) * S_) * D_;

    // ---- async loads: Q (64x64), K band (192x64); rows stride 144B --------
#pragma unroll
    for (int it = 0; it < 2; it++) {
        int idx = tid + it * 256;
        int row = idx >> 3, dc = (idx & 7) * 8;
        uint32_t so = sb + AT_QH + row * 144 + dc * 2;
        long g = base + (long)(s0 + row) * D_ + dc;
        cpa16(so, g_qh + g);
        cpa16(so + (AT_QL - AT_QH), g_ql + g);
    }
#pragma unroll
    for (int it = 0; it < 6; it++) {
        int idx = tid + it * 256;
        int jr = idx >> 3, dc = (idx & 7) * 8;
        int kg = s0 - (W_ - 1) + jr;
        uint32_t ok = (kg >= 0) ? 16u : 0u;
        long g = base + (long)(kg >= 0 ? kg : 0) * D_ + dc;
        uint32_t sk = sb + AT_KH + jr * 144 + dc * 2;
        cpa16z(sk,         g_kh + g, ok);
        cpa16z(sk + 27648, g_kl + g, ok);
    }
    asm volatile("cp.async.commit_group;" ::: "memory");
    asm volatile("cp.async.wait_group 0;" ::: "memory");
    __syncthreads();

    // ---- phase 1: S = Q K^T ----------------------------------------------
    float sacc[12][4];
#pragma unroll
    for (int i = 0; i < 12; i++)
#pragma unroll
        for (int e = 0; e < 4; e++) sacc[i][e] = 0.f;

    {
        const int arow = wm * 16 + (lane & 15);
        const int akoff = (lane >> 4) * 8;
        const int brL = ((lane >> 4) ? 8 : 0) + (lane & 7);
        const int bkoff = ((lane >> 3) & 1) * 8;
#pragma unroll
        for (int ks = 0; ks < 4; ks++) {
            uint32_t aq = sb + AT_QH + (arow * 72 + ks * 16 + akoff) * 2;
            uint32_t a_h[4], a_l[4];
            LDSM4(a_h, aq);
            LDSM4(a_l, aq + (AT_QL - AT_QH));
#pragma unroll
            for (int nb = 0; nb < 6; nb++) {
                int nrow = wn * 96 + nb * 16 + brL;
                uint32_t bk = sb + AT_KH + (nrow * 72 + ks * 16 + bkoff) * 2;
                uint32_t b_h[4], b_l[4];
                LDSM4(b_h, bk);
                LDSM4(b_l, bk + 27648);
                MMA16816(sacc[nb * 2 + 0], a_h, b_h[0], b_h[1]);
                MMA16816(sacc[nb * 2 + 0], a_h, b_l[0], b_l[1]);
                MMA16816(sacc[nb * 2 + 0], a_l, b_h[0], b_h[1]);
                MMA16816(sacc[nb * 2 + 1], a_h, b_h[2], b_h[3]);
                MMA16816(sacc[nb * 2 + 1], a_h, b_l[2], b_l[3]);
                MMA16816(sacc[nb * 2 + 1], a_l, b_h[2], b_h[3]);
            }
        }
    }
    __syncthreads();   // all warps done reading K; V may overwrite it

    // ---- issue V loads into K's smem (hidden under softmax) ---------------
#pragma unroll
    for (int it = 0; it < 6; it++) {
        int idx = tid + it * 256;
        int jr = idx >> 3, dc = (idx & 7) * 8;
        int kg = s0 - (W_ - 1) + jr;
        uint32_t ok = (kg >= 0) ? 16u : 0u;
        long g = base + (long)(kg >= 0 ? kg : 0) * D_ + dc;
        uint32_t sv = sb + AT_VH + jr * 144 + dc * 2;
        cpa16z(sv,         g_vh + g, ok);
        cpa16z(sv + 27648, g_vl + g, ok);
    }
    asm volatile("cp.async.commit_group;" ::: "memory");

    // ---- mask + scale in registers ----------------------------------------
    const int i_t = wm * 16 + (lane >> 2);
    const int i_b = i_t + 8;
    const int lo_t = (i_t > (W_ - 1) - s0) ? i_t : ((W_ - 1) - s0);
    const int hi_t = i_t + (W_ - 1);
    const int lo_b = (i_b > (W_ - 1) - s0) ? i_b : ((W_ - 1) - s0);
    const int hi_b = i_b + (W_ - 1);
#pragma unroll
    for (int t = 0; t < 12; t++) {
        int j0 = wn * 96 + t * 8 + (lane & 3) * 2;
        float* c = sacc[t];
        c[0] = (j0     >= lo_t && j0     <= hi_t) ? c[0] * 0.125f : -3.0e38f;
        c[1] = (j0 + 1 >= lo_t && j0 + 1 <= hi_t) ? c[1] * 0.125f : -3.0e38f;
        c[2] = (j0     >= lo_b && j0     <= hi_b) ? c[2] * 0.125f : -3.0e38f;
        c[3] = (j0 + 1 >= lo_b && j0 + 1 <= hi_b) ? c[3] * 0.125f : -3.0e38f;
    }

    // ---- register softmax with cross-warp reduction -----------------------
    float* Red = (float*)(smc + AT_RED);
    float mt = -3.0e38f, mb = -3.0e38f;
#pragma unroll
    for (int t = 0; t < 12; t++) {
        mt = fmaxf(mt, fmaxf(sacc[t][0], sacc[t][1]));
        mb = fmaxf(mb, fmaxf(sacc[t][2], sacc[t][3]));
    }
    mt = fmaxf(mt, __shfl_xor_sync(0xffffffffu, mt, 1));
    mt = fmaxf(mt, __shfl_xor_sync(0xffffffffu, mt, 2));
    mb = fmaxf(mb, __shfl_xor_sync(0xffffffffu, mb, 1));
    mb = fmaxf(mb, __shfl_xor_sync(0xffffffffu, mb, 2));
    if ((lane & 3) == 0) {
        Red[wn * 64 + i_t] = mt;
        Red[wn * 64 + i_b] = mb;
    }
    __syncthreads();
    const float Mt = fmaxf(Red[i_t], Red[64 + i_t]);
    const float Mb = fmaxf(Red[i_b], Red[64 + i_b]);

    float st = 0.f, sbt = 0.f;
#pragma unroll
    for (int t = 0; t < 12; t++) {
        float* c = sacc[t];
        c[0] = __expf(c[0] - Mt);
        c[1] = __expf(c[1] - Mt);
        c[2] = __expf(c[2] - Mb);
        c[3] = __expf(c[3] - Mb);
        st  += c[0] + c[1];
        sbt += c[2] + c[3];
    }
    st  += __shfl_xor_sync(0xffffffffu, st, 1);
    st  += __shfl_xor_sync(0xffffffffu, st, 2);
    sbt += __shfl_xor_sync(0xffffffffu, sbt, 1);
    sbt += __shfl_xor_sync(0xffffffffu, sbt, 2);
    if ((lane & 3) == 0) {
        Red[128 + wn * 64 + i_t] = st;
        Red[128 + wn * 64 + i_b] = sbt;
    }
    __syncthreads();
    const float inv_t = 1.0f / (Red[128 + i_t] + Red[192 + i_t]);
    const float inv_b = 1.0f / (Red[128 + i_b] + Red[192 + i_b]);

    // ---- P fragments -> split-bf16 A fragments (registers) ----------------
    uint32_t pah[6][4], pal[6][4];
#pragma unroll
    for (int ks = 0; ks < 6; ks++) {
        float* c0 = sacc[2 * ks];
        float* c1 = sacc[2 * ks + 1];
        __nv_bfloat16 h00, h01, h02, h03, h10, h11, h12, h13;
        __nv_bfloat16 l00, l01, l02, l03, l10, l11, l12, l13;
        split_bf16(c0[0] * inv_t, h00, l00);
        split_bf16(c0[1] * inv_t, h01, l01);
        split_bf16(c0[2] * inv_b, h02, l02);
        split_bf16(c0[3] * inv_b, h03, l03);
        split_bf16(c1[0] * inv_t, h10, l10);
        split_bf16(c1[1] * inv_t, h11, l11);
        split_bf16(c1[2] * inv_b, h12, l12);
        split_bf16(c1[3] * inv_b, h13, l13);
        pah[ks][0] = pkbf(h00, h01); pah[ks][1] = pkbf(h02, h03);
        pah[ks][2] = pkbf(h10, h11); pah[ks][3] = pkbf(h12, h13);
        pal[ks][0] = pkbf(l00, l01); pal[ks][1] = pkbf(l02, l03);
        pal[ks][2] = pkbf(l10, l11); pal[ks][3] = pkbf(l12, l13);
    }

    // ---- wait for V, then phase 3: partial O = P_half * V_half ------------
    asm volatile("cp.async.wait_group 0;" ::: "memory");
    __syncthreads();

    float oacc[8][4];
#pragma unroll
    for (int i = 0; i < 8; i++)
#pragma unroll
        for (int e = 0; e < 4; e++) oacc[i][e] = 0.f;

    {
        const int jrow = wn * 96 + (lane & 15);
        const int dsel = (lane >> 4) * 8;
#pragma unroll
        for (int ks = 0; ks < 6; ks++) {
#pragma unroll
            for (int db = 0; db < 4; db++) {
                uint32_t bv = sb + AT_VH + ((jrow + ks * 16) * 72 + db * 16 + dsel) * 2;
                uint32_t b_h[4], b_l[4];
                LDSM4T(b_h, bv);
                LDSM4T(b_l, bv + 27648);
                MMA16816(oacc[db * 2 + 0], pah[ks], b_h[0], b_h[1]);
                MMA16816(oacc[db * 2 + 0], pah[ks], b_l[0], b_l[1]);
                MMA16816(oacc[db * 2 + 0], pal[ks], b_h[0], b_h[1]);
                MMA16816(oacc[db * 2 + 1], pah[ks], b_h[2], b_h[3]);
                MMA16816(oacc[db * 2 + 1], pah[ks], b_l[2], b_l[3]);
                MMA16816(oacc[db * 2 + 1], pal[ks], b_h[2], b_h[3]);
            }
        }
    }
    __syncthreads();   // all V reads done; Obuf may alias Q/V smem

    // ---- combine wn-half partials via smem --------------------------------
    float* Obuf = (float*)smc + wn * (64 * 66);
#pragma unroll
    for (int t = 0; t < 8; t++) {
        int d = t * 8 + (lane & 3) * 2;
        *(float2*)(Obuf + i_t * 66 + d) = make_float2(oacc[t][0], oacc[t][1]);
        *(float2*)(Obuf + i_b * 66 + d) = make_float2(oacc[t][2], oacc[t][3]);
    }
    __syncthreads();

    float* Ob0 = (float*)smc;
    float* Ob1 = (float*)smc + 64 * 66;
#pragma unroll
    for (int it = 0; it < 2; it++) {
        int idx = tid + it * 256;
        int row = idx >> 3, dg = (idx & 7) * 8;
        __nv_bfloat16 hh[8], ll[8];
#pragma unroll
        for (int e = 0; e < 8; e++) {
            float v = Ob0[row * 66 + dg + e] + Ob1[row * 66 + dg + e];
            split_bf16(v, hh[e], ll[e]);
        }
        long gidx = ((long)(b * S_ + s0 + row)) * DM_ + h * D_ + dg;
        *(uint4*)(g_ah + gidx) = *(uint4*)hh;
        *(uint4*)(g_al + gidx) = *(uint4*)ll;
    }
}

// ---------------------------------------------------------------------------
extern "C" void kernel_launch(void* const* d_in, const int* in_sizes, int n_in,
                              void* d_out, int out_size)
{
    const float* x  = (const float*)d_in[0];
    const float* Wq = (const float*)d_in[1];
    const float* Wk = (const float*)d_in[2];
    const float* Wv = (const float*)d_in[3];
    const float* Wo = (const float*)d_in[4];
    float* out = (float*)d_out;

    cudaFuncSetAttribute(mma_gemm_qkv, cudaFuncAttributeMaxDynamicSharedMemorySize, GSM_BYTES);
    cudaFuncSetAttribute(mma_gemm_out, cudaFuncAttributeMaxDynamicSharedMemorySize, GSM_BYTES);
    cudaFuncSetAttribute(attn_k, cudaFuncAttributeMaxDynamicSharedMemorySize, AT_BYTES);

    conv_k<<<3072, 256>>>(x, Wq, Wk, Wv, Wo);
    mma_gemm_qkv<<<dim3(12, 32), 256, GSM_BYTES>>>();
    attn_k<<<dim3(S_ / 64, H_, B_), 256, AT_BYTES>>>();
    mma_gemm_out<<<dim3(4, 32), 256, GSM_BYTES>>>(out);
}